// round 8
// baseline (speedup 1.0000x reference)
#include <cuda_runtime.h>
#include <cuda_fp16.h>
#include <cstdint>

#define TS   2048
#define HD   1024
#define FFD  1024
#define NE   16
#define NK   4
#define NCH  16                        // K chunks of 64 halfs
#define ARB  144                       // A smem row bytes (64 halfs + pad)
#define BRB  528                       // B smem row bytes (256 halfs + pad)
#define ATILE (128 * ARB)              // 18432
#define BTILE (64 * BRB)               // 33792
#define STAGE (ATILE + BTILE)          // 52224
#define DSMEM (3 * STAGE)              // 156672
#define CST  264                       // epilogue C stride (floats)

#define CW1_BLOCKS 32768               // Win conv blocks  (33.55M elems / 4 / 256)
#define CW2_BLOCKS 16384               // Wout conv blocks (16.78M elems / 4 / 256)
#define PRE_BLOCKS (CW1_BLOCKS + CW2_BLOCKS + TS)

// ---------------- scratch (device globals) ----------------
struct Ctr { int counts[NE]; float imp[NE]; int loadcnt[NK]; };
__device__ Ctr    g_ctr;
__device__ int    g_tok[NE][TS];
__device__ float  g_gate[NE][TS];
__device__ __half g_xh[(size_t)TS * HD];               // x fp16
__device__ __half g_win_h[(size_t)NE * HD * 2 * FFD];  // W_in fp16, original [e][k][n]
__device__ __half g_wout_h[(size_t)NE * FFD * HD];     // W_out fp16, original [e][k][n]
__device__ __half g_act_h[(size_t)NE * TS * FFD];      // activations fp16

// ---------------- helpers ----------------
__device__ __forceinline__ void mma_f16(float d[4], const uint32_t a[4], const uint32_t b[2]) {
    asm volatile(
        "mma.sync.aligned.m16n8k16.row.col.f32.f16.f16.f32 "
        "{%0,%1,%2,%3}, {%4,%5,%6,%7}, {%8,%9}, {%0,%1,%2,%3};"
        : "+f"(d[0]), "+f"(d[1]), "+f"(d[2]), "+f"(d[3])
        : "r"(a[0]), "r"(a[1]), "r"(a[2]), "r"(a[3]), "r"(b[0]), "r"(b[1]));
}
__device__ __forceinline__ void ldsm4(uint32_t r[4], uint32_t addr) {
    asm volatile("ldmatrix.sync.aligned.m8n8.x4.shared.b16 {%0,%1,%2,%3}, [%4];"
        : "=r"(r[0]), "=r"(r[1]), "=r"(r[2]), "=r"(r[3]) : "r"(addr));
}
__device__ __forceinline__ void ldsm4t(uint32_t r[4], uint32_t addr) {
    asm volatile("ldmatrix.sync.aligned.m8n8.x4.trans.shared.b16 {%0,%1,%2,%3}, [%4];"
        : "=r"(r[0]), "=r"(r[1]), "=r"(r[2]), "=r"(r[3]) : "r"(addr));
}
__device__ __forceinline__ uint32_t s2u(const void* p) {
    return (uint32_t)__cvta_generic_to_shared(p);
}
__device__ __forceinline__ void cpa16(uint32_t dst, const void* src) {
    asm volatile("cp.async.ca.shared.global [%0], [%1], 16;" :: "r"(dst), "l"(src));
}
__device__ __forceinline__ void cpa_commit() { asm volatile("cp.async.commit_group;"); }
template<int N> __device__ __forceinline__ void cpa_wait() {
    asm volatile("cp.async.wait_group %0;" :: "n"(N));
}
union H2U2 { __half2 h[2]; uint2 u; };

// ---------------- fused pre-kernel: Win conv | Wout conv | router ----------------
__global__ void __launch_bounds__(256) pre_kernel(const float* __restrict__ x,
                                                  const float* __restrict__ Win,
                                                  const float* __restrict__ Wout,
                                                  const float* __restrict__ rw,
                                                  const float* __restrict__ rb) {
    const int b = blockIdx.x, tid = threadIdx.x;
    if (b < CW1_BLOCKS + CW2_BLOCKS) {
        // weight fp32 -> fp16 convert (layout preserved)
        const float* src; __half* dst; size_t i;
        if (b < CW1_BLOCKS) { src = Win; dst = g_win_h; i = ((size_t)b * 256 + tid) * 4; }
        else { src = Wout; dst = g_wout_h; i = ((size_t)(b - CW1_BLOCKS) * 256 + tid) * 4; }
        float4 v = *(const float4*)(src + i);
        H2U2 pk;
        pk.h[0] = __floats2half2_rn(v.x, v.y);
        pk.h[1] = __floats2half2_rn(v.z, v.w);
        *(uint2*)(dst + i) = pk.u;
        return;
    }
    // ---- router block (one token) ----
    __shared__ float xs[HD];
    __shared__ float lg[NE];
    const int s = b - (CW1_BLOCKS + CW2_BLOCKS);
    const float* xrow = x + (size_t)s * HD;
    for (int i = tid; i < HD / 4; i += 256)
        ((float4*)xs)[i] = ((const float4*)xrow)[i];
    __syncthreads();
    for (int i = tid; i < HD / 2; i += 256) {
        float2 v = ((const float2*)xs)[i];
        ((__half2*)(g_xh + (size_t)s * HD))[i] = __floats2half2_rn(v.x, v.y);
    }
    const int w = tid >> 5, lane = tid & 31;
    for (int e = w; e < NE; e += 8) {
        const float* r = rw + (size_t)e * HD;
        float p = 0.f;
        for (int i = lane; i < HD; i += 32) p += xs[i] * r[i];
        #pragma unroll
        for (int o = 16; o; o >>= 1) p += __shfl_xor_sync(0xFFFFFFFFu, p, o);
        if (lane == 0) lg[e] = p + rb[e];
    }
    __syncthreads();
    if (tid == 0) {
        float v[NE];
        #pragma unroll
        for (int e = 0; e < NE; e++) v[e] = lg[e];
        int idx[NK]; float tv[NK]; bool used[NE];
        #pragma unroll
        for (int e = 0; e < NE; e++) used[e] = false;
        for (int k = 0; k < NK; k++) {
            int bi = 0; float bv = -3.0e38f;
            for (int e = 0; e < NE; e++)
                if (!used[e] && v[e] > bv) { bv = v[e]; bi = e; }
            used[bi] = true; idx[k] = bi; tv[k] = bv;
        }
        float w4[NK], den = 0.f, m = tv[0];
        for (int k = 0; k < NK; k++) { w4[k] = expf(tv[k] - m); den += w4[k]; }
        for (int k = 0; k < NK; k++) w4[k] /= den;
        float mm = v[0];
        for (int e = 1; e < NE; e++) mm = fmaxf(mm, v[e]);
        float pr[NE], d2 = 0.f;
        for (int e = 0; e < NE; e++) { pr[e] = expf(v[e] - mm); d2 += pr[e]; }
        for (int e = 0; e < NE; e++) atomicAdd(&g_ctr.imp[e], pr[e] / d2);
        int jm = 0;
        for (int k = 1; k < NK; k++) if (idx[k] > idx[jm]) jm = k;
        atomicAdd(&g_ctr.loadcnt[jm], 1);
        for (int k = 0; k < NK; k++) {
            int e = idx[k];
            int slot = atomicAdd(&g_ctr.counts[e], 1);
            g_tok[e][slot]  = s;
            g_gate[e][slot] = w4[k];
        }
    }
}

// ---------------- GEMM1: 128m x 256n (128 up + 128 gate), warp 64x64, fused SwiGLU ----------------
__global__ void __launch_bounds__(256, 1) g1_kernel(const float* __restrict__ bin) {
    extern __shared__ __align__(16) char dsm[];
    __shared__ int toks[128];
    __shared__ float bUs[128], bGs[128];
    const int e = blockIdx.z, m0 = blockIdx.x * 128, nf0 = blockIdx.y * 128;
    const int cnt = g_ctr.counts[e];
    if (m0 >= cnt) return;
    const int tid = threadIdx.x;
    if (tid < 128) {
        int r = m0 + tid;
        toks[tid] = (r < cnt) ? g_tok[e][r] : g_tok[e][0];
        bUs[tid] = bin[(size_t)e * 2 * FFD + nf0 + tid];
    } else {
        bGs[tid - 128] = bin[(size_t)e * 2 * FFD + FFD + nf0 + (tid - 128)];
    }
    __syncthreads();

    const uint32_t smu = s2u(dsm);
    const __half* Wb = g_win_h + (size_t)e * HD * (2 * FFD);

    auto load_chunk = [&](int c, int s) {
        const int k0 = c * 64;
        const uint32_t ab = smu + (uint32_t)s * STAGE, bb = ab + ATILE;
        #pragma unroll
        for (int g = 0; g < 4; g++) {
            int gg = g * 256 + tid, r = gg >> 3, cc = gg & 7;
            cpa16(ab + (uint32_t)(r * ARB + cc * 16),
                  g_xh + (size_t)toks[r] * HD + k0 + cc * 8);
        }
        #pragma unroll
        for (int g = 0; g < 8; g++) {
            int gg = g * 256 + tid, r = gg >> 5, g32 = gg & 31;
            int n = (g32 < 16) ? (nf0 + g32 * 8) : (FFD + nf0 + (g32 - 16) * 8);
            cpa16(bb + (uint32_t)(r * BRB + g32 * 16),
                  Wb + (size_t)(k0 + r) * (2 * FFD) + n);
        }
        cpa_commit();
    };

    const int wid = tid >> 5, lane = tid & 31;
    const int wm = wid >> 2, wn = wid & 3;
    const int gq = lane >> 2, tg = lane & 3;
    const int rsel = lane & 7, seg = (lane >> 3) & 1, hsel = lane >> 4;
    const uint32_t aoff = (uint32_t)((rsel + seg * 8) * ARB + hsel * 16);
    const uint32_t boff = (uint32_t)((lane & 15) * BRB + (lane >> 4) * 16);
    float acc[4][8][4] = {};

    load_chunk(0, 0); load_chunk(1, 1);
    #pragma unroll 1
    for (int c = 0; c < NCH; c++) {
        if (c == NCH - 1) cpa_wait<0>(); else cpa_wait<1>();
        __syncthreads();
        if (c + 2 < NCH) load_chunk(c + 2, (c + 2) % 3);
        const uint32_t st = smu + (uint32_t)(c % 3) * STAGE;
        const uint32_t abase = st + (uint32_t)(wm * 64 * ARB) + aoff;
        const uint32_t bbase = st + ATILE + (uint32_t)(wn * 128) + boff;
        #pragma unroll
        for (int k16 = 0; k16 < 4; k16++) {
            uint32_t a[4][4];
            #pragma unroll
            for (int i = 0; i < 4; i++) ldsm4(a[i], abase + i * 16 * ARB + k16 * 32);
            #pragma unroll
            for (int j2 = 0; j2 < 4; j2++) {
                uint32_t b4[4];
                ldsm4t(b4, bbase + k16 * 16 * BRB + j2 * 32);
                #pragma unroll
                for (int i = 0; i < 4; i++) {
                    mma_f16(acc[i][2*j2],     a[i], &b4[0]);
                    mma_f16(acc[i][2*j2 + 1], a[i], &b4[2]);
                }
            }
        }
    }
    __syncthreads();

    float* Cs = (float*)dsm;
    #pragma unroll
    for (int i = 0; i < 4; i++) {
        #pragma unroll
        for (int j = 0; j < 8; j++) {
            int r0 = wm * 64 + i * 16 + gq, c0 = wn * 64 + j * 8 + 2 * tg;
            *(float2*)&Cs[r0 * CST + c0]       = make_float2(acc[i][j][0], acc[i][j][1]);
            *(float2*)&Cs[(r0 + 8) * CST + c0] = make_float2(acc[i][j][2], acc[i][j][3]);
        }
    }
    __syncthreads();
    const int mlim = cnt - m0;
    #pragma unroll
    for (int it = 0; it < 16; it++) {
        int idx = it * 256 + tid, row = idx >> 5, fc = (idx & 31) * 4;
        if (row < mlim) {
            float4 u4 = *(float4*)&Cs[row * CST + fc];
            float4 g4 = *(float4*)&Cs[row * CST + 128 + fc];
            float uu[4] = {u4.x, u4.y, u4.z, u4.w};
            float gg[4] = {g4.x, g4.y, g4.z, g4.w};
            float o[4];
            #pragma unroll
            for (int q = 0; q < 4; q++) {
                float up = fminf(fmaxf(uu[q] + bUs[fc + q], -7.f), 7.f);
                float gt = fminf(fmaxf(gg[q] + bGs[fc + q], -7.f), 7.f);
                o[q] = gt / (1.f + expf(-gt)) * up;
            }
            H2U2 pk;
            pk.h[0] = __floats2half2_rn(o[0], o[1]);
            pk.h[1] = __floats2half2_rn(o[2], o[3]);
            *(uint2*)(g_act_h + ((size_t)e * TS + m0 + row) * FFD + nf0 + fc) = pk.u;
        }
    }
}

// ---------------- GEMM2: 128m x 256n, warp 64x64, weighted atomic scatter + aux ----------------
__global__ void __launch_bounds__(256, 1) g2_kernel(const float* __restrict__ bout,
                                                    float* __restrict__ out, int out_size) {
    extern __shared__ __align__(16) char dsm[];
    __shared__ int toks[128];
    __shared__ float gws[128];
    const int e = blockIdx.z, m0 = blockIdx.x * 128, n0 = blockIdx.y * 256;
    const int tid = threadIdx.x;
    // aux-loss scalar (router done before this kernel)
    if (e == 0 && blockIdx.x == 0 && blockIdx.y == 0 && tid == 0 && out_size > TS * HD) {
        float a = 0.f;
        #pragma unroll
        for (int j = 0; j < NK; j++)
            a += (g_ctr.imp[j] / (float)TS) * ((float)g_ctr.loadcnt[j] / (float)TS);
        out[TS * HD] = 0.02f * (float)NE * a;
    }
    const int cnt = g_ctr.counts[e];
    if (m0 >= cnt) return;
    if (tid < 128) {
        int r = m0 + tid;
        toks[tid] = (r < cnt) ? g_tok[e][r] : 0;
        gws[tid]  = (r < cnt) ? g_gate[e][r] : 0.f;
    }
    __syncthreads();

    const uint32_t smu = s2u(dsm);
    const __half* Wb = g_wout_h + (size_t)e * FFD * HD;
    const __half* Arows = g_act_h + ((size_t)e * TS + m0) * FFD;

    auto load_chunk = [&](int c, int s) {
        const int k0 = c * 64;
        const uint32_t ab = smu + (uint32_t)s * STAGE, bb = ab + ATILE;
        #pragma unroll
        for (int g = 0; g < 4; g++) {
            int gg = g * 256 + tid, r = gg >> 3, cc = gg & 7;
            cpa16(ab + (uint32_t)(r * ARB + cc * 16),
                  Arows + (size_t)r * FFD + k0 + cc * 8);
        }
        #pragma unroll
        for (int g = 0; g < 8; g++) {
            int gg = g * 256 + tid, r = gg >> 5, g32 = gg & 31;
            cpa16(bb + (uint32_t)(r * BRB + g32 * 16),
                  Wb + (size_t)(k0 + r) * HD + n0 + g32 * 8);
        }
        cpa_commit();
    };

    const int wid = tid >> 5, lane = tid & 31;
    const int wm = wid >> 2, wn = wid & 3;
    const int gq = lane >> 2, tg = lane & 3;
    const int rsel = lane & 7, seg = (lane >> 3) & 1, hsel = lane >> 4;
    const uint32_t aoff = (uint32_t)((rsel + seg * 8) * ARB + hsel * 16);
    const uint32_t boff = (uint32_t)((lane & 15) * BRB + (lane >> 4) * 16);
    float acc[4][8][4] = {};

    load_chunk(0, 0); load_chunk(1, 1);
    #pragma unroll 1
    for (int c = 0; c < NCH; c++) {
        if (c == NCH - 1) cpa_wait<0>(); else cpa_wait<1>();
        __syncthreads();
        if (c + 2 < NCH) load_chunk(c + 2, (c + 2) % 3);
        const uint32_t st = smu + (uint32_t)(c % 3) * STAGE;
        const uint32_t abase = st + (uint32_t)(wm * 64 * ARB) + aoff;
        const uint32_t bbase = st + ATILE + (uint32_t)(wn * 128) + boff;
        #pragma unroll
        for (int k16 = 0; k16 < 4; k16++) {
            uint32_t a[4][4];
            #pragma unroll
            for (int i = 0; i < 4; i++) ldsm4(a[i], abase + i * 16 * ARB + k16 * 32);
            #pragma unroll
            for (int j2 = 0; j2 < 4; j2++) {
                uint32_t b4[4];
                ldsm4t(b4, bbase + k16 * 16 * BRB + j2 * 32);
                #pragma unroll
                for (int i = 0; i < 4; i++) {
                    mma_f16(acc[i][2*j2],     a[i], &b4[0]);
                    mma_f16(acc[i][2*j2 + 1], a[i], &b4[2]);
                }
            }
        }
    }

    const float* bo = bout + (size_t)e * HD + n0;
    #pragma unroll
    for (int i = 0; i < 4; i++) {
        int r0 = wm * 64 + i * 16 + gq;
        #pragma unroll
        for (int h = 0; h < 2; h++) {
            int row = r0 + h * 8;
            if (m0 + row < cnt) {
                float gw = gws[row];
                float* orow = out + (size_t)toks[row] * HD + n0;
                #pragma unroll
                for (int j = 0; j < 8; j++) {
                    int c0 = wn * 64 + j * 8 + 2 * tg;
                    atomicAdd(&orow[c0],     gw * (acc[i][j][2 * h]     + bo[c0]));
                    atomicAdd(&orow[c0 + 1], gw * (acc[i][j][2 * h + 1] + bo[c0 + 1]));
                }
            }
        }
    }
}

// ---------------- launcher ----------------
extern "C" void kernel_launch(void* const* d_in, const int* in_sizes, int n_in,
                              void* d_out, int out_size) {
    const float* x    = (const float*)d_in[0];
    const float* Win  = (const float*)d_in[1];
    const float* bin  = (const float*)d_in[2];
    const float* Wout = (const float*)d_in[3];
    const float* bout = (const float*)d_in[4];
    const float* rw   = (const float*)d_in[5];
    const float* rb   = (const float*)d_in[6];
    float* out = (float*)d_out;

    cudaFuncSetAttribute(g1_kernel, cudaFuncAttributeMaxDynamicSharedMemorySize, DSMEM);
    cudaFuncSetAttribute(g2_kernel, cudaFuncAttributeMaxDynamicSharedMemorySize, DSMEM);

    void* ctr_addr;
    cudaGetSymbolAddress(&ctr_addr, g_ctr);

    cudaMemsetAsync(d_out, 0, (size_t)out_size * sizeof(float));              // node 1
    cudaMemsetAsync(ctr_addr, 0, sizeof(Ctr));                                // node 2
    pre_kernel<<<PRE_BLOCKS, 256>>>(x, Win, Wout, rw, rb);                    // node 3
    g1_kernel<<<dim3(TS / 128, FFD / 128, NE), 256, DSMEM>>>(bin);            // node 4
    g2_kernel<<<dim3(TS / 128, HD / 256, NE), 256, DSMEM>>>(bout, out, out_size); // node 5 <- profiled
}

// round 9
// speedup vs baseline: 1.0386x; 1.0386x over previous
#include <cuda_runtime.h>
#include <cuda_fp16.h>
#include <cstdint>

#define TS   2048
#define HD   1024
#define FFD  1024
#define NE   16
#define NK   4
#define NCH  16                        // K chunks of 64 halfs
#define ARB  144                       // A smem row bytes (64 halfs + pad)
#define BRB  528                       // B smem row bytes (256 halfs + pad)
#define ATILE (128 * ARB)              // 18432
#define BTILE (64 * BRB)               // 33792
#define STAGE (ATILE + BTILE)          // 52224
#define DSMEM (3 * STAGE)              // 156672
#define CST  264                       // epilogue C stride (floats)

// ---------------- scratch (device globals) ----------------
struct Ctr { int counts[NE]; float imp[NE]; int loadcnt[NK]; };
__device__ Ctr    g_ctr;
__device__ int    g_tok[NE][TS];
__device__ float  g_gate[NE][TS];
__device__ __half g_xh[(size_t)TS * HD];               // x fp16
__device__ __half g_win_h[(size_t)NE * HD * 2 * FFD];  // W_in fp16, original [e][k][n]
__device__ __half g_wout_h[(size_t)NE * FFD * HD];     // W_out fp16, original [e][k][n]
__device__ __half g_act_h[(size_t)NE * TS * FFD];      // activations fp16

// ---------------- helpers ----------------
__device__ __forceinline__ void mma_f16(float d[4], const uint32_t a[4], const uint32_t b[2]) {
    asm volatile(
        "mma.sync.aligned.m16n8k16.row.col.f32.f16.f16.f32 "
        "{%0,%1,%2,%3}, {%4,%5,%6,%7}, {%8,%9}, {%0,%1,%2,%3};"
        : "+f"(d[0]), "+f"(d[1]), "+f"(d[2]), "+f"(d[3])
        : "r"(a[0]), "r"(a[1]), "r"(a[2]), "r"(a[3]), "r"(b[0]), "r"(b[1]));
}
__device__ __forceinline__ void ldsm4(uint32_t r[4], uint32_t addr) {
    asm volatile("ldmatrix.sync.aligned.m8n8.x4.shared.b16 {%0,%1,%2,%3}, [%4];"
        : "=r"(r[0]), "=r"(r[1]), "=r"(r[2]), "=r"(r[3]) : "r"(addr));
}
__device__ __forceinline__ void ldsm4t(uint32_t r[4], uint32_t addr) {
    asm volatile("ldmatrix.sync.aligned.m8n8.x4.trans.shared.b16 {%0,%1,%2,%3}, [%4];"
        : "=r"(r[0]), "=r"(r[1]), "=r"(r[2]), "=r"(r[3]) : "r"(addr));
}
__device__ __forceinline__ uint32_t s2u(const void* p) {
    return (uint32_t)__cvta_generic_to_shared(p);
}
__device__ __forceinline__ void cpa16(uint32_t dst, const void* src) {
    asm volatile("cp.async.ca.shared.global [%0], [%1], 16;" :: "r"(dst), "l"(src));
}
__device__ __forceinline__ void cpa_commit() { asm volatile("cp.async.commit_group;"); }
template<int N> __device__ __forceinline__ void cpa_wait() {
    asm volatile("cp.async.wait_group %0;" :: "n"(N));
}
union H2U2 { __half2 h[2]; uint2 u; };

// ---------------- kernel: elementwise fp32 -> fp16 convert (keeps layout) ----------------
__global__ void conv_kernel(const float* __restrict__ W, __half* __restrict__ Wh) {
    size_t i = ((size_t)blockIdx.x * 256 + threadIdx.x) * 4;
    float4 v = *(const float4*)(W + i);
    H2U2 pk;
    pk.h[0] = __floats2half2_rn(v.x, v.y);
    pk.h[1] = __floats2half2_rn(v.z, v.w);
    *(uint2*)(Wh + i) = pk.u;
}

// ---------------- kernel: router + gating + aux stats + scatter + x->fp16 ----------------
__global__ void router_kernel(const float* __restrict__ x,
                              const float* __restrict__ rw,
                              const float* __restrict__ rb) {
    __shared__ float xs[HD];
    __shared__ float lg[NE];
    const int s = blockIdx.x, tid = threadIdx.x;
    const float* xrow = x + (size_t)s * HD;
    for (int i = tid; i < HD / 4; i += 128)
        ((float4*)xs)[i] = ((const float4*)xrow)[i];
    __syncthreads();
    for (int i = tid; i < HD / 2; i += 128) {
        float2 v = ((const float2*)xs)[i];
        ((__half2*)(g_xh + (size_t)s * HD))[i] = __floats2half2_rn(v.x, v.y);
    }
    const int w = tid >> 5, lane = tid & 31;
    for (int e = w; e < NE; e += 4) {
        const float* r = rw + (size_t)e * HD;
        float p = 0.f;
        for (int i = lane; i < HD; i += 32) p += xs[i] * r[i];
        #pragma unroll
        for (int o = 16; o; o >>= 1) p += __shfl_xor_sync(0xFFFFFFFFu, p, o);
        if (lane == 0) lg[e] = p + rb[e];
    }
    __syncthreads();
    if (tid == 0) {
        float v[NE];
        #pragma unroll
        for (int e = 0; e < NE; e++) v[e] = lg[e];
        int idx[NK]; float tv[NK]; bool used[NE];
        #pragma unroll
        for (int e = 0; e < NE; e++) used[e] = false;
        for (int k = 0; k < NK; k++) {
            int bi = 0; float bv = -3.0e38f;
            for (int e = 0; e < NE; e++)
                if (!used[e] && v[e] > bv) { bv = v[e]; bi = e; }
            used[bi] = true; idx[k] = bi; tv[k] = bv;
        }
        float w4[NK], den = 0.f, m = tv[0];
        for (int k = 0; k < NK; k++) { w4[k] = expf(tv[k] - m); den += w4[k]; }
        for (int k = 0; k < NK; k++) w4[k] /= den;
        float mm = v[0];
        for (int e = 1; e < NE; e++) mm = fmaxf(mm, v[e]);
        float pr[NE], d2 = 0.f;
        for (int e = 0; e < NE; e++) { pr[e] = expf(v[e] - mm); d2 += pr[e]; }
        for (int e = 0; e < NE; e++) atomicAdd(&g_ctr.imp[e], pr[e] / d2);
        int jm = 0;
        for (int k = 1; k < NK; k++) if (idx[k] > idx[jm]) jm = k;
        atomicAdd(&g_ctr.loadcnt[jm], 1);
        for (int k = 0; k < NK; k++) {
            int e = idx[k];
            int slot = atomicAdd(&g_ctr.counts[e], 1);
            g_tok[e][slot]  = s;
            g_gate[e][slot] = w4[k];
        }
    }
}

// ---------------- GEMM1: 128m x 256n (128 up + 128 gate), warp 64x64, fused SwiGLU ----------------
__global__ void __launch_bounds__(256, 1) g1_kernel(const float* __restrict__ bin) {
    extern __shared__ __align__(16) char dsm[];
    __shared__ int toks[128];
    __shared__ float bUs[128], bGs[128];
    const int e = blockIdx.z, m0 = blockIdx.x * 128, nf0 = blockIdx.y * 128;
    const int cnt = g_ctr.counts[e];
    if (m0 >= cnt) return;
    const int tid = threadIdx.x;
    if (tid < 128) {
        int r = m0 + tid;
        toks[tid] = (r < cnt) ? g_tok[e][r] : g_tok[e][0];
        bUs[tid] = bin[(size_t)e * 2 * FFD + nf0 + tid];
    } else {
        bGs[tid - 128] = bin[(size_t)e * 2 * FFD + FFD + nf0 + (tid - 128)];
    }
    __syncthreads();

    const uint32_t smu = s2u(dsm);
    const __half* Wb = g_win_h + (size_t)e * HD * (2 * FFD);

    auto load_chunk = [&](int c, int s) {
        const int k0 = c * 64;
        const uint32_t ab = smu + (uint32_t)s * STAGE, bb = ab + ATILE;
        #pragma unroll
        for (int g = 0; g < 4; g++) {
            int gg = g * 256 + tid, r = gg >> 3, cc = gg & 7;
            cpa16(ab + (uint32_t)(r * ARB + cc * 16),
                  g_xh + (size_t)toks[r] * HD + k0 + cc * 8);
        }
        #pragma unroll
        for (int g = 0; g < 8; g++) {
            int gg = g * 256 + tid, r = gg >> 5, g32 = gg & 31;
            int n = (g32 < 16) ? (nf0 + g32 * 8) : (FFD + nf0 + (g32 - 16) * 8);
            cpa16(bb + (uint32_t)(r * BRB + g32 * 16),
                  Wb + (size_t)(k0 + r) * (2 * FFD) + n);
        }
        cpa_commit();
    };

    const int wid = tid >> 5, lane = tid & 31;
    const int wm = wid >> 2, wn = wid & 3;
    const int gq = lane >> 2, tg = lane & 3;
    const int rsel = lane & 7, seg = (lane >> 3) & 1, hsel = lane >> 4;
    const uint32_t aoff = (uint32_t)((rsel + seg * 8) * ARB + hsel * 16);
    const uint32_t boff = (uint32_t)((lane & 15) * BRB + (lane >> 4) * 16);
    float acc[4][8][4] = {};

    load_chunk(0, 0); load_chunk(1, 1);
    #pragma unroll 1
    for (int c = 0; c < NCH; c++) {
        if (c == NCH - 1) cpa_wait<0>(); else cpa_wait<1>();
        __syncthreads();
        if (c + 2 < NCH) load_chunk(c + 2, (c + 2) % 3);
        const uint32_t st = smu + (uint32_t)(c % 3) * STAGE;
        const uint32_t abase = st + (uint32_t)(wm * 64 * ARB) + aoff;
        const uint32_t bbase = st + ATILE + (uint32_t)(wn * 128) + boff;
        #pragma unroll
        for (int k16 = 0; k16 < 4; k16++) {
            uint32_t a[4][4];
            #pragma unroll
            for (int i = 0; i < 4; i++) ldsm4(a[i], abase + i * 16 * ARB + k16 * 32);
            #pragma unroll
            for (int j2 = 0; j2 < 4; j2++) {
                uint32_t b4[4];
                ldsm4t(b4, bbase + k16 * 16 * BRB + j2 * 32);
                #pragma unroll
                for (int i = 0; i < 4; i++) {
                    mma_f16(acc[i][2*j2],     a[i], &b4[0]);
                    mma_f16(acc[i][2*j2 + 1], a[i], &b4[2]);
                }
            }
        }
    }
    __syncthreads();

    float* Cs = (float*)dsm;
    #pragma unroll
    for (int i = 0; i < 4; i++) {
        #pragma unroll
        for (int j = 0; j < 8; j++) {
            int r0 = wm * 64 + i * 16 + gq, c0 = wn * 64 + j * 8 + 2 * tg;
            *(float2*)&Cs[r0 * CST + c0]       = make_float2(acc[i][j][0], acc[i][j][1]);
            *(float2*)&Cs[(r0 + 8) * CST + c0] = make_float2(acc[i][j][2], acc[i][j][3]);
        }
    }
    __syncthreads();
    const int mlim = cnt - m0;
    #pragma unroll
    for (int it = 0; it < 16; it++) {
        int idx = it * 256 + tid, row = idx >> 5, fc = (idx & 31) * 4;
        if (row < mlim) {
            float4 u4 = *(float4*)&Cs[row * CST + fc];
            float4 g4 = *(float4*)&Cs[row * CST + 128 + fc];
            float uu[4] = {u4.x, u4.y, u4.z, u4.w};
            float gg[4] = {g4.x, g4.y, g4.z, g4.w};
            float o[4];
            #pragma unroll
            for (int q = 0; q < 4; q++) {
                float up = fminf(fmaxf(uu[q] + bUs[fc + q], -7.f), 7.f);
                float gt = fminf(fmaxf(gg[q] + bGs[fc + q], -7.f), 7.f);
                o[q] = gt / (1.f + expf(-gt)) * up;
            }
            H2U2 pk;
            pk.h[0] = __floats2half2_rn(o[0], o[1]);
            pk.h[1] = __floats2half2_rn(o[2], o[3]);
            *(uint2*)(g_act_h + ((size_t)e * TS + m0 + row) * FFD + nf0 + fc) = pk.u;
        }
    }
}

// ---------------- GEMM2: 128m x 256n, warp 64x64, weighted atomic scatter + aux ----------------
__global__ void __launch_bounds__(256, 1) g2_kernel(const float* __restrict__ bout,
                                                    float* __restrict__ out, int out_size) {
    extern __shared__ __align__(16) char dsm[];
    __shared__ int toks[128];
    __shared__ float gws[128];
    const int e = blockIdx.z, m0 = blockIdx.x * 128, n0 = blockIdx.y * 256;
    const int tid = threadIdx.x;
    if (e == 0 && blockIdx.x == 0 && blockIdx.y == 0 && tid == 0 && out_size > TS * HD) {
        float a = 0.f;
        #pragma unroll
        for (int j = 0; j < NK; j++)
            a += (g_ctr.imp[j] / (float)TS) * ((float)g_ctr.loadcnt[j] / (float)TS);
        out[TS * HD] = 0.02f * (float)NE * a;
    }
    const int cnt = g_ctr.counts[e];
    if (m0 >= cnt) return;
    if (tid < 128) {
        int r = m0 + tid;
        toks[tid] = (r < cnt) ? g_tok[e][r] : 0;
        gws[tid]  = (r < cnt) ? g_gate[e][r] : 0.f;
    }
    __syncthreads();

    const uint32_t smu = s2u(dsm);
    const __half* Wb = g_wout_h + (size_t)e * FFD * HD;
    const __half* Arows = g_act_h + ((size_t)e * TS + m0) * FFD;

    auto load_chunk = [&](int c, int s) {
        const int k0 = c * 64;
        const uint32_t ab = smu + (uint32_t)s * STAGE, bb = ab + ATILE;
        #pragma unroll
        for (int g = 0; g < 4; g++) {
            int gg = g * 256 + tid, r = gg >> 3, cc = gg & 7;
            cpa16(ab + (uint32_t)(r * ARB + cc * 16),
                  Arows + (size_t)r * FFD + k0 + cc * 8);
        }
        #pragma unroll
        for (int g = 0; g < 8; g++) {
            int gg = g * 256 + tid, r = gg >> 5, g32 = gg & 31;
            cpa16(bb + (uint32_t)(r * BRB + g32 * 16),
                  Wb + (size_t)(k0 + r) * HD + n0 + g32 * 8);
        }
        cpa_commit();
    };

    const int wid = tid >> 5, lane = tid & 31;
    const int wm = wid >> 2, wn = wid & 3;
    const int gq = lane >> 2, tg = lane & 3;
    const int rsel = lane & 7, seg = (lane >> 3) & 1, hsel = lane >> 4;
    const uint32_t aoff = (uint32_t)((rsel + seg * 8) * ARB + hsel * 16);
    const uint32_t boff = (uint32_t)((lane & 15) * BRB + (lane >> 4) * 16);
    float acc[4][8][4] = {};

    load_chunk(0, 0); load_chunk(1, 1);
    #pragma unroll 1
    for (int c = 0; c < NCH; c++) {
        if (c == NCH - 1) cpa_wait<0>(); else cpa_wait<1>();
        __syncthreads();
        if (c + 2 < NCH) load_chunk(c + 2, (c + 2) % 3);
        const uint32_t st = smu + (uint32_t)(c % 3) * STAGE;
        const uint32_t abase = st + (uint32_t)(wm * 64 * ARB) + aoff;
        const uint32_t bbase = st + ATILE + (uint32_t)(wn * 128) + boff;
        #pragma unroll
        for (int k16 = 0; k16 < 4; k16++) {
            uint32_t a[4][4];
            #pragma unroll
            for (int i = 0; i < 4; i++) ldsm4(a[i], abase + i * 16 * ARB + k16 * 32);
            #pragma unroll
            for (int j2 = 0; j2 < 4; j2++) {
                uint32_t b4[4];
                ldsm4t(b4, bbase + k16 * 16 * BRB + j2 * 32);
                #pragma unroll
                for (int i = 0; i < 4; i++) {
                    mma_f16(acc[i][2*j2],     a[i], &b4[0]);
                    mma_f16(acc[i][2*j2 + 1], a[i], &b4[2]);
                }
            }
        }
    }

    const float* bo = bout + (size_t)e * HD + n0;
    #pragma unroll
    for (int i = 0; i < 4; i++) {
        int r0 = wm * 64 + i * 16 + gq;
        #pragma unroll
        for (int h = 0; h < 2; h++) {
            int row = r0 + h * 8;
            if (m0 + row < cnt) {
                float gw = gws[row];
                float* orow = out + (size_t)toks[row] * HD + n0;
                #pragma unroll
                for (int j = 0; j < 8; j++) {
                    int c0 = wn * 64 + j * 8 + 2 * tg;
                    atomicAdd(&orow[c0],     gw * (acc[i][j][2 * h]     + bo[c0]));
                    atomicAdd(&orow[c0 + 1], gw * (acc[i][j][2 * h + 1] + bo[c0 + 1]));
                }
            }
        }
    }
}

// ---------------- launcher: event-forked two-stream DAG ----------------
extern "C" void kernel_launch(void* const* d_in, const int* in_sizes, int n_in,
                              void* d_out, int out_size) {
    const float* x    = (const float*)d_in[0];
    const float* Win  = (const float*)d_in[1];
    const float* bin  = (const float*)d_in[2];
    const float* Wout = (const float*)d_in[3];
    const float* bout = (const float*)d_in[4];
    const float* rw   = (const float*)d_in[5];
    const float* rb   = (const float*)d_in[6];
    float* out = (float*)d_out;

    cudaFuncSetAttribute(g1_kernel, cudaFuncAttributeMaxDynamicSharedMemorySize, DSMEM);
    cudaFuncSetAttribute(g2_kernel, cudaFuncAttributeMaxDynamicSharedMemorySize, DSMEM);

    void* ctr_addr;
    cudaGetSymbolAddress(&ctr_addr, g_ctr);
    __half* winh; __half* wouth;
    cudaGetSymbolAddress((void**)&winh,  g_win_h);
    cudaGetSymbolAddress((void**)&wouth, g_wout_h);

    cudaStream_t s1;
    cudaStreamCreateWithFlags(&s1, cudaStreamNonBlocking);
    cudaEvent_t eFork, eRt, eW2;
    cudaEventCreateWithFlags(&eFork, cudaEventDisableTiming);
    cudaEventCreateWithFlags(&eRt,   cudaEventDisableTiming);
    cudaEventCreateWithFlags(&eW2,   cudaEventDisableTiming);

    // stream 0: memsets, then fork
    cudaMemsetAsync(d_out, 0, (size_t)out_size * sizeof(float));
    cudaMemsetAsync(ctr_addr, 0, sizeof(Ctr));
    cudaEventRecord(eFork, 0);
    cudaStreamWaitEvent(s1, eFork, 0);

    // s1: router (needs ctr zeroed), then conv_Wout — both off the critical conv_Win path
    router_kernel<<<TS, 128, 0, s1>>>(x, rw, rb);
    conv_kernel<<<NE * FFD * HD / 1024, 256, 0, s1>>>(Wout, wouth);
    cudaEventRecord(eRt, s1);   // router done (recorded after conv_Wout issued; conv_Wout ordered after router on s1)

    // stream 0: conv_Win concurrent with router
    conv_kernel<<<NE * HD * 2 * FFD / 1024, 256>>>(Win, winh);

    // g1 needs: conv_Win (stream order) + router + (s1 ordering also gives conv_Wout, acceptable)
    cudaStreamWaitEvent(0, eRt, 0);
    g1_kernel<<<dim3(TS / 128, FFD / 128, NE), 256, DSMEM>>>(bin);

    // g2 needs g1 (stream order) + conv_Wout (already ordered via eRt wait above)
    g2_kernel<<<dim3(TS / 128, HD / 256, NE), 256, DSMEM>>>(bout, out, out_size);

    cudaEventRecord(eW2, 0);    // keep s1 alive until graph end for clean capture join
    cudaStreamWaitEvent(s1, eW2, 0);

    cudaEventDestroy(eFork);
    cudaEventDestroy(eRt);
    cudaEventDestroy(eW2);
    cudaStreamDestroy(s1);
}

// round 10
// speedup vs baseline: 1.0405x; 1.0019x over previous
#include <cuda_runtime.h>
#include <cuda_fp16.h>
#include <cstdint>

#define TS   2048
#define HD   1024
#define FFD  1024
#define NE   16
#define NK   4
#define NCH  16                        // K chunks of 64 halfs
#define ARB  144                       // A smem row bytes (64 halfs + pad)
#define BRB  528                       // B smem row bytes (256 halfs + pad)
#define ATILE (128 * ARB)              // 18432
#define BTILE (64 * BRB)               // 33792
#define STAGE (ATILE + BTILE)          // 52224
#define DSMEM (3 * STAGE)              // 156672

// ---------------- scratch (device globals) ----------------
struct Ctr { int counts[NE]; float imp[NE]; int loadcnt[NK]; };
__device__ Ctr    g_ctr;
__device__ int    g_tok[NE][TS];
__device__ float  g_gate[NE][TS];
__device__ __half g_xh[(size_t)TS * HD];               // x fp16
__device__ __half g_win_h[(size_t)NE * HD * 2 * FFD];  // W_in fp16, original [e][k][n]
__device__ __half g_wout_h[(size_t)NE * FFD * HD];     // W_out fp16, original [e][k][n]
__device__ __half g_act_h[(size_t)NE * TS * FFD];      // activations fp16

// ---------------- helpers ----------------
__device__ __forceinline__ void mma_f16(float d[4], const uint32_t a[4], const uint32_t b[2]) {
    asm volatile(
        "mma.sync.aligned.m16n8k16.row.col.f32.f16.f16.f32 "
        "{%0,%1,%2,%3}, {%4,%5,%6,%7}, {%8,%9}, {%0,%1,%2,%3};"
        : "+f"(d[0]), "+f"(d[1]), "+f"(d[2]), "+f"(d[3])
        : "r"(a[0]), "r"(a[1]), "r"(a[2]), "r"(a[3]), "r"(b[0]), "r"(b[1]));
}
__device__ __forceinline__ void ldsm4(uint32_t r[4], uint32_t addr) {
    asm volatile("ldmatrix.sync.aligned.m8n8.x4.shared.b16 {%0,%1,%2,%3}, [%4];"
        : "=r"(r[0]), "=r"(r[1]), "=r"(r[2]), "=r"(r[3]) : "r"(addr));
}
__device__ __forceinline__ void ldsm4t(uint32_t r[4], uint32_t addr) {
    asm volatile("ldmatrix.sync.aligned.m8n8.x4.trans.shared.b16 {%0,%1,%2,%3}, [%4];"
        : "=r"(r[0]), "=r"(r[1]), "=r"(r[2]), "=r"(r[3]) : "r"(addr));
}
__device__ __forceinline__ uint32_t s2u(const void* p) {
    return (uint32_t)__cvta_generic_to_shared(p);
}
__device__ __forceinline__ void cpa16(uint32_t dst, const void* src) {
    asm volatile("cp.async.ca.shared.global [%0], [%1], 16;" :: "r"(dst), "l"(src));
}
__device__ __forceinline__ void cpa_commit() { asm volatile("cp.async.commit_group;"); }
template<int N> __device__ __forceinline__ void cpa_wait() {
    asm volatile("cp.async.wait_group %0;" :: "n"(N));
}
union H4U4 { __half2 h[4]; uint4 u; };

// ---------------- kernel: merged weight fp32 -> fp16 convert (both W_in, W_out) ----------------
__global__ void conv_kernel(const float* __restrict__ Win, const float* __restrict__ Wout) {
    const size_t NW1 = (size_t)NE * HD * 2 * FFD;     // 33554432 (block-aligned at 2048)
    size_t i = ((size_t)blockIdx.x * 256 + threadIdx.x) * 8;
    const float* src; __half* dst;
    if (i < NW1) { src = Win + i;         dst = g_win_h + i; }
    else         { src = Wout + (i - NW1); dst = g_wout_h + (i - NW1); }
    float4 a = *(const float4*)src;
    float4 b = *(const float4*)(src + 4);
    H4U4 pk;
    pk.h[0] = __floats2half2_rn(a.x, a.y);
    pk.h[1] = __floats2half2_rn(a.z, a.w);
    pk.h[2] = __floats2half2_rn(b.x, b.y);
    pk.h[3] = __floats2half2_rn(b.z, b.w);
    *(uint4*)dst = pk.u;
}

// ---------------- kernel: router + gating + aux stats + scatter + x->fp16 ----------------
__global__ void router_kernel(const float* __restrict__ x,
                              const float* __restrict__ rw,
                              const float* __restrict__ rb) {
    __shared__ float xs[HD];
    __shared__ float lg[NE];
    const int s = blockIdx.x, tid = threadIdx.x;
    const float* xrow = x + (size_t)s * HD;
    for (int i = tid; i < HD / 4; i += 128)
        ((float4*)xs)[i] = ((const float4*)xrow)[i];
    __syncthreads();
    for (int i = tid; i < HD / 2; i += 128) {
        float2 v = ((const float2*)xs)[i];
        ((__half2*)(g_xh + (size_t)s * HD))[i] = __floats2half2_rn(v.x, v.y);
    }
    const int w = tid >> 5, lane = tid & 31;
    for (int e = w; e < NE; e += 4) {
        const float* r = rw + (size_t)e * HD;
        float p = 0.f;
        for (int i = lane; i < HD; i += 32) p += xs[i] * r[i];
        #pragma unroll
        for (int o = 16; o; o >>= 1) p += __shfl_xor_sync(0xFFFFFFFFu, p, o);
        if (lane == 0) lg[e] = p + rb[e];
    }
    __syncthreads();
    if (tid == 0) {
        float v[NE];
        #pragma unroll
        for (int e = 0; e < NE; e++) v[e] = lg[e];
        int idx[NK]; float tv[NK]; bool used[NE];
        #pragma unroll
        for (int e = 0; e < NE; e++) used[e] = false;
        for (int k = 0; k < NK; k++) {
            int bi = 0; float bv = -3.0e38f;
            for (int e = 0; e < NE; e++)
                if (!used[e] && v[e] > bv) { bv = v[e]; bi = e; }
            used[bi] = true; idx[k] = bi; tv[k] = bv;
        }
        float w4[NK], den = 0.f, m = tv[0];
        for (int k = 0; k < NK; k++) { w4[k] = expf(tv[k] - m); den += w4[k]; }
        for (int k = 0; k < NK; k++) w4[k] /= den;
        float mm = v[0];
        for (int e = 1; e < NE; e++) mm = fmaxf(mm, v[e]);
        float pr[NE], d2 = 0.f;
        for (int e = 0; e < NE; e++) { pr[e] = expf(v[e] - mm); d2 += pr[e]; }
        for (int e = 0; e < NE; e++) atomicAdd(&g_ctr.imp[e], pr[e] / d2);
        int jm = 0;
        for (int k = 1; k < NK; k++) if (idx[k] > idx[jm]) jm = k;
        atomicAdd(&g_ctr.loadcnt[jm], 1);
        for (int k = 0; k < NK; k++) {
            int e = idx[k];
            int slot = atomicAdd(&g_ctr.counts[e], 1);
            g_tok[e][slot]  = s;
            g_gate[e][slot] = w4[k];
        }
    }
}

// ---------------- GEMM1: 128m x 128f, B interleaved (up|gate per 8-col granule) ----------------
// B smem cols: granule 2t = up f [t*8, t*8+8), granule 2t+1 = gate same f range.
// => each thread's acc[i][2p] (up) and acc[i][2p+1] (gate) cover the SAME f values:
//    register-resident SwiGLU, coalesced half2 stores, no smem staging.
__global__ void __launch_bounds__(256, 1) g1_kernel(const float* __restrict__ bin) {
    extern __shared__ __align__(16) char dsm[];
    __shared__ int toks[128];
    __shared__ float bUs[128], bGs[128];
    const int e = blockIdx.z, m0 = blockIdx.x * 128, nf0 = blockIdx.y * 128;
    const int cnt = g_ctr.counts[e];
    if (m0 >= cnt) return;
    const int tid = threadIdx.x;
    if (tid < 128) {
        int r = m0 + tid;
        toks[tid] = (r < cnt) ? g_tok[e][r] : g_tok[e][0];
        bUs[tid] = bin[(size_t)e * 2 * FFD + nf0 + tid];
    } else {
        bGs[tid - 128] = bin[(size_t)e * 2 * FFD + FFD + nf0 + (tid - 128)];
    }
    __syncthreads();

    const uint32_t smu = s2u(dsm);
    const __half* Wb = g_win_h + (size_t)e * HD * (2 * FFD);

    auto load_chunk = [&](int c, int s) {
        const int k0 = c * 64;
        const uint32_t ab = smu + (uint32_t)s * STAGE, bb = ab + ATILE;
        #pragma unroll
        for (int g = 0; g < 4; g++) {
            int gg = g * 256 + tid, r = gg >> 3, cc = gg & 7;
            cpa16(ab + (uint32_t)(r * ARB + cc * 16),
                  g_xh + (size_t)toks[r] * HD + k0 + cc * 8);
        }
        #pragma unroll
        for (int g = 0; g < 8; g++) {
            int gg = g * 256 + tid, r = gg >> 5, g32 = gg & 31;
            int t = g32 >> 1;
            int n = ((g32 & 1) == 0) ? (nf0 + t * 8) : (FFD + nf0 + t * 8);
            cpa16(bb + (uint32_t)(r * BRB + g32 * 16),
                  Wb + (size_t)(k0 + r) * (2 * FFD) + n);
        }
        cpa_commit();
    };

    const int wid = tid >> 5, lane = tid & 31;
    const int wm = wid >> 2, wn = wid & 3;
    const int gq = lane >> 2, tg = lane & 3;
    const int rsel = lane & 7, seg = (lane >> 3) & 1, hsel = lane >> 4;
    const uint32_t aoff = (uint32_t)((rsel + seg * 8) * ARB + hsel * 16);
    const uint32_t boff = (uint32_t)((lane & 15) * BRB + (lane >> 4) * 16);
    float acc[4][8][4] = {};

    load_chunk(0, 0); load_chunk(1, 1);
    #pragma unroll 1
    for (int c = 0; c < NCH; c++) {
        if (c == NCH - 1) cpa_wait<0>(); else cpa_wait<1>();
        __syncthreads();
        if (c + 2 < NCH) load_chunk(c + 2, (c + 2) % 3);
        const uint32_t st = smu + (uint32_t)(c % 3) * STAGE;
        const uint32_t abase = st + (uint32_t)(wm * 64 * ARB) + aoff;
        const uint32_t bbase = st + ATILE + (uint32_t)(wn * 128) + boff;
        #pragma unroll
        for (int k16 = 0; k16 < 4; k16++) {
            uint32_t a[4][4];
            #pragma unroll
            for (int i = 0; i < 4; i++) ldsm4(a[i], abase + i * 16 * ARB + k16 * 32);
            #pragma unroll
            for (int j2 = 0; j2 < 4; j2++) {
                uint32_t b4[4];
                ldsm4t(b4, bbase + k16 * 16 * BRB + j2 * 32);
                #pragma unroll
                for (int i = 0; i < 4; i++) {
                    mma_f16(acc[i][2*j2],     a[i], &b4[0]);
                    mma_f16(acc[i][2*j2 + 1], a[i], &b4[2]);
                }
            }
        }
    }

    // register-resident SwiGLU epilogue, coalesced half2 stores
    const int mlim = cnt - m0;
    float2 bu[4], bg[4];
    #pragma unroll
    for (int p = 0; p < 4; p++) {
        int f0 = wn * 32 + p * 8 + 2 * tg;
        bu[p] = *(float2*)&bUs[f0];
        bg[p] = *(float2*)&bGs[f0];
    }
    #pragma unroll
    for (int i = 0; i < 4; i++) {
        int r0 = wm * 64 + i * 16 + gq;
        #pragma unroll
        for (int h = 0; h < 2; h++) {
            int row = r0 + h * 8;
            if (row < mlim) {
                __half* arow = g_act_h + ((size_t)e * TS + m0 + row) * FFD + nf0;
                #pragma unroll
                for (int p = 0; p < 4; p++) {
                    int f0 = wn * 32 + p * 8 + 2 * tg;
                    float up0 = acc[i][2*p][2*h]     + bu[p].x;
                    float up1 = acc[i][2*p][2*h + 1] + bu[p].y;
                    float gt0 = acc[i][2*p+1][2*h]     + bg[p].x;
                    float gt1 = acc[i][2*p+1][2*h + 1] + bg[p].y;
                    up0 = fminf(fmaxf(up0, -7.f), 7.f);
                    up1 = fminf(fmaxf(up1, -7.f), 7.f);
                    gt0 = fminf(fmaxf(gt0, -7.f), 7.f);
                    gt1 = fminf(fmaxf(gt1, -7.f), 7.f);
                    float o0 = gt0 / (1.f + expf(-gt0)) * up0;
                    float o1 = gt1 / (1.f + expf(-gt1)) * up1;
                    *(__half2*)(arow + f0) = __floats2half2_rn(o0, o1);
                }
            }
        }
    }
}

// ---------------- GEMM2: 128m x 256n, warp 64x64, weighted atomic scatter + aux ----------------
__global__ void __launch_bounds__(256, 1) g2_kernel(const float* __restrict__ bout,
                                                    float* __restrict__ out, int out_size) {
    extern __shared__ __align__(16) char dsm[];
    __shared__ int toks[128];
    __shared__ float gws[128];
    const int e = blockIdx.z, m0 = blockIdx.x * 128, n0 = blockIdx.y * 256;
    const int tid = threadIdx.x;
    if (e == 0 && blockIdx.x == 0 && blockIdx.y == 0 && tid == 0 && out_size > TS * HD) {
        float a = 0.f;
        #pragma unroll
        for (int j = 0; j < NK; j++)
            a += (g_ctr.imp[j] / (float)TS) * ((float)g_ctr.loadcnt[j] / (float)TS);
        out[TS * HD] = 0.02f * (float)NE * a;
    }
    const int cnt = g_ctr.counts[e];
    if (m0 >= cnt) return;
    if (tid < 128) {
        int r = m0 + tid;
        toks[tid] = (r < cnt) ? g_tok[e][r] : 0;
        gws[tid]  = (r < cnt) ? g_gate[e][r] : 0.f;
    }
    __syncthreads();

    const uint32_t smu = s2u(dsm);
    const __half* Wb = g_wout_h + (size_t)e * FFD * HD;
    const __half* Arows = g_act_h + ((size_t)e * TS + m0) * FFD;

    auto load_chunk = [&](int c, int s) {
        const int k0 = c * 64;
        const uint32_t ab = smu + (uint32_t)s * STAGE, bb = ab + ATILE;
        #pragma unroll
        for (int g = 0; g < 4; g++) {
            int gg = g * 256 + tid, r = gg >> 3, cc = gg & 7;
            cpa16(ab + (uint32_t)(r * ARB + cc * 16),
                  Arows + (size_t)r * FFD + k0 + cc * 8);
        }
        #pragma unroll
        for (int g = 0; g < 8; g++) {
            int gg = g * 256 + tid, r = gg >> 5, g32 = gg & 31;
            cpa16(bb + (uint32_t)(r * BRB + g32 * 16),
                  Wb + (size_t)(k0 + r) * HD + n0 + g32 * 8);
        }
        cpa_commit();
    };

    const int wid = tid >> 5, lane = tid & 31;
    const int wm = wid >> 2, wn = wid & 3;
    const int gq = lane >> 2, tg = lane & 3;
    const int rsel = lane & 7, seg = (lane >> 3) & 1, hsel = lane >> 4;
    const uint32_t aoff = (uint32_t)((rsel + seg * 8) * ARB + hsel * 16);
    const uint32_t boff = (uint32_t)((lane & 15) * BRB + (lane >> 4) * 16);
    float acc[4][8][4] = {};

    load_chunk(0, 0); load_chunk(1, 1);
    #pragma unroll 1
    for (int c = 0; c < NCH; c++) {
        if (c == NCH - 1) cpa_wait<0>(); else cpa_wait<1>();
        __syncthreads();
        if (c + 2 < NCH) load_chunk(c + 2, (c + 2) % 3);
        const uint32_t st = smu + (uint32_t)(c % 3) * STAGE;
        const uint32_t abase = st + (uint32_t)(wm * 64 * ARB) + aoff;
        const uint32_t bbase = st + ATILE + (uint32_t)(wn * 128) + boff;
        #pragma unroll
        for (int k16 = 0; k16 < 4; k16++) {
            uint32_t a[4][4];
            #pragma unroll
            for (int i = 0; i < 4; i++) ldsm4(a[i], abase + i * 16 * ARB + k16 * 32);
            #pragma unroll
            for (int j2 = 0; j2 < 4; j2++) {
                uint32_t b4[4];
                ldsm4t(b4, bbase + k16 * 16 * BRB + j2 * 32);
                #pragma unroll
                for (int i = 0; i < 4; i++) {
                    mma_f16(acc[i][2*j2],     a[i], &b4[0]);
                    mma_f16(acc[i][2*j2 + 1], a[i], &b4[2]);
                }
            }
        }
    }

    const float* bo = bout + (size_t)e * HD + n0;
    #pragma unroll
    for (int i = 0; i < 4; i++) {
        int r0 = wm * 64 + i * 16 + gq;
        #pragma unroll
        for (int h = 0; h < 2; h++) {
            int row = r0 + h * 8;
            if (m0 + row < cnt) {
                float gw = gws[row];
                float* orow = out + (size_t)toks[row] * HD + n0;
                #pragma unroll
                for (int j = 0; j < 8; j++) {
                    int c0 = wn * 64 + j * 8 + 2 * tg;
                    atomicAdd(&orow[c0],     gw * (acc[i][j][2 * h]     + bo[c0]));
                    atomicAdd(&orow[c0 + 1], gw * (acc[i][j][2 * h + 1] + bo[c0 + 1]));
                }
            }
        }
    }
}

// ---------------- launcher (single stream; overlap proved worthless — all pre-kernels BW-bound) ----------------
extern "C" void kernel_launch(void* const* d_in, const int* in_sizes, int n_in,
                              void* d_out, int out_size) {
    const float* x    = (const float*)d_in[0];
    const float* Win  = (const float*)d_in[1];
    const float* bin  = (const float*)d_in[2];
    const float* Wout = (const float*)d_in[3];
    const float* bout = (const float*)d_in[4];
    const float* rw   = (const float*)d_in[5];
    const float* rb   = (const float*)d_in[6];
    float* out = (float*)d_out;

    cudaFuncSetAttribute(g1_kernel, cudaFuncAttributeMaxDynamicSharedMemorySize, DSMEM);
    cudaFuncSetAttribute(g2_kernel, cudaFuncAttributeMaxDynamicSharedMemorySize, DSMEM);

    void* ctr_addr;
    cudaGetSymbolAddress(&ctr_addr, g_ctr);

    const int conv_blocks = (NE * HD * 2 * FFD + NE * FFD * HD) / 8 / 256;  // 24576

    cudaMemsetAsync(d_out, 0, (size_t)out_size * sizeof(float));
    cudaMemsetAsync(ctr_addr, 0, sizeof(Ctr));
    conv_kernel<<<conv_blocks, 256>>>(Win, Wout);                               // 1
    router_kernel<<<TS, 128>>>(x, rw, rb);                                      // 2
    g1_kernel<<<dim3(TS / 128, FFD / 128, NE), 256, DSMEM>>>(bin);              // 3
    g2_kernel<<<dim3(TS / 128, HD / 256, NE), 256, DSMEM>>>(bout, out, out_size); // 4 <- profiled
}

// round 15
// speedup vs baseline: 1.0656x; 1.0241x over previous
#include <cuda_runtime.h>
#include <cuda_fp16.h>
#include <cstdint>

#define TS   2048
#define HD   1024
#define FFD  1024
#define NE   16
#define NK   4
#define NCH  16                        // K chunks of 64 halfs
#define ARB  144                       // A smem row bytes (64 halfs + pad)
#define BRB  528                       // B smem row bytes (256 halfs + pad)
#define ATILE (128 * ARB)              // 18432
#define BTILE (64 * BRB)               // 33792
#define STAGE (ATILE + BTILE)          // 52224
#define DSMEM (3 * STAGE)              // 156672
#define RTOK 8                         // tokens per router block

// ---------------- scratch (device globals) ----------------
struct Ctr { int counts[NE]; float imp[NE]; int loadcnt[NK]; };
__device__ Ctr    g_ctr;
__device__ int    g_tok[NE][TS];
__device__ float  g_gate[NE][TS];
__device__ __half g_xh[(size_t)TS * HD];               // x fp16
__device__ __half g_win_h[(size_t)NE * HD * 2 * FFD];  // W_in fp16, original [e][k][n]
__device__ __half g_wout_h[(size_t)NE * FFD * HD];     // W_out fp16, original [e][k][n]
__device__ __half g_act_h[(size_t)NE * TS * FFD];      // activations fp16

// ---------------- helpers ----------------
__device__ __forceinline__ void mma_f16(float d[4], const uint32_t a[4], const uint32_t b[2]) {
    asm volatile(
        "mma.sync.aligned.m16n8k16.row.col.f32.f16.f16.f32 "
        "{%0,%1,%2,%3}, {%4,%5,%6,%7}, {%8,%9}, {%0,%1,%2,%3};"
        : "+f"(d[0]), "+f"(d[1]), "+f"(d[2]), "+f"(d[3])
        : "r"(a[0]), "r"(a[1]), "r"(a[2]), "r"(a[3]), "r"(b[0]), "r"(b[1]));
}
__device__ __forceinline__ void ldsm4(uint32_t r[4], uint32_t addr) {
    asm volatile("ldmatrix.sync.aligned.m8n8.x4.shared.b16 {%0,%1,%2,%3}, [%4];"
        : "=r"(r[0]), "=r"(r[1]), "=r"(r[2]), "=r"(r[3]) : "r"(addr));
}
__device__ __forceinline__ void ldsm4t(uint32_t r[4], uint32_t addr) {
    asm volatile("ldmatrix.sync.aligned.m8n8.x4.trans.shared.b16 {%0,%1,%2,%3}, [%4];"
        : "=r"(r[0]), "=r"(r[1]), "=r"(r[2]), "=r"(r[3]) : "r"(addr));
}
__device__ __forceinline__ uint32_t s2u(const void* p) {
    return (uint32_t)__cvta_generic_to_shared(p);
}
__device__ __forceinline__ void cpa16(uint32_t dst, const void* src) {
    asm volatile("cp.async.ca.shared.global [%0], [%1], 16;" :: "r"(dst), "l"(src));
}
__device__ __forceinline__ void cpa_commit() { asm volatile("cp.async.commit_group;"); }
template<int N> __device__ __forceinline__ void cpa_wait() {
    asm volatile("cp.async.wait_group %0;" :: "n"(N));
}
union H4U4 { __half2 h[4]; uint4 u; };

// ---------------- kernel: weight fp32->fp16 convert + ctr zero + d_out zero ----------------
__global__ void conv_kernel(const float* __restrict__ Win, const float* __restrict__ Wout,
                            float* __restrict__ out, int out_size, int wblocks) {
    const int b = blockIdx.x, tid = threadIdx.x;
    // FIX (R14 bug): zero ALL sizeof(Ctr)/4 = 36 words — the old `tid < 32` gate
    // left loadcnt[] unzeroed, accumulating across graph replays.
    if (b == 0 && tid < (int)(sizeof(Ctr) / 4)) {
        ((int*)&g_ctr)[tid] = 0;
    }
    if (b < wblocks) {
        const size_t NW1 = (size_t)NE * HD * 2 * FFD;
        size_t i = ((size_t)b * 256 + tid) * 8;
        const float* src; __half* dst;
        if (i < NW1) { src = Win + i;          dst = g_win_h + i; }
        else         { src = Wout + (i - NW1); dst = g_wout_h + (i - NW1); }
        float4 a = *(const float4*)src;
        float4 c = *(const float4*)(src + 4);
        H4U4 pk;
        pk.h[0] = __floats2half2_rn(a.x, a.y);
        pk.h[1] = __floats2half2_rn(a.z, a.w);
        pk.h[2] = __floats2half2_rn(c.x, c.y);
        pk.h[3] = __floats2half2_rn(c.z, c.w);
        *(uint4*)dst = pk.u;
    } else {
        // zero d_out (including the aux element at TS*HD)
        int i = (b - wblocks) * 2048 + tid * 8;
        if (i + 8 <= out_size) {
            *(float4*)(out + i)     = make_float4(0.f, 0.f, 0.f, 0.f);
            *(float4*)(out + i + 4) = make_float4(0.f, 0.f, 0.f, 0.f);
        } else {
            for (int j = 0; j < 8; j++)
                if (i + j < out_size) out[i + j] = 0.f;
        }
    }
}

// ---------------- kernel: router, 8 tokens/block, rw in registers ----------------
__global__ void __launch_bounds__(256) router_kernel(const float* __restrict__ x,
                                                     const float* __restrict__ rw,
                                                     const float* __restrict__ rb) {
    __shared__ float xs[RTOK][HD];
    __shared__ float lg[RTOK][NE];
    const int s0 = blockIdx.x * RTOK, tid = threadIdx.x;
    for (int i = tid; i < RTOK * HD / 4; i += 256)
        ((float4*)xs)[i] = ((const float4*)(x + (size_t)s0 * HD))[i];
    __syncthreads();
    for (int i = tid; i < RTOK * HD / 2; i += 256) {
        float2 v = ((const float2*)xs)[i];
        ((__half2*)(g_xh + (size_t)s0 * HD))[i] = __floats2half2_rn(v.x, v.y);
    }
    const int w = tid >> 5, lane = tid & 31;
    #pragma unroll
    for (int ee = 0; ee < 2; ee++) {
        const int e = w * 2 + ee;
        const float* r = rw + (size_t)e * HD;
        float rreg[32];
        #pragma unroll
        for (int j = 0; j < 32; j++) rreg[j] = r[lane + 32 * j];
        #pragma unroll
        for (int t = 0; t < RTOK; t++) {
            float p = 0.f;
            #pragma unroll
            for (int j = 0; j < 32; j++) p += rreg[j] * xs[t][lane + 32 * j];
            #pragma unroll
            for (int o = 16; o; o >>= 1) p += __shfl_xor_sync(0xFFFFFFFFu, p, o);
            if (lane == 0) lg[t][e] = p + rb[e];
        }
    }
    __syncthreads();
    if (tid < RTOK) {
        const int s = s0 + tid;
        float v[NE];
        #pragma unroll
        for (int e = 0; e < NE; e++) v[e] = lg[tid][e];
        int idx[NK]; float tv[NK]; bool used[NE];
        #pragma unroll
        for (int e = 0; e < NE; e++) used[e] = false;
        for (int k = 0; k < NK; k++) {
            int bi = 0; float bv = -3.0e38f;
            for (int e = 0; e < NE; e++)
                if (!used[e] && v[e] > bv) { bv = v[e]; bi = e; }
            used[bi] = true; idx[k] = bi; tv[k] = bv;
        }
        float w4[NK], den = 0.f, m = tv[0];
        for (int k = 0; k < NK; k++) { w4[k] = expf(tv[k] - m); den += w4[k]; }
        for (int k = 0; k < NK; k++) w4[k] /= den;
        float mm = v[0];
        for (int e = 1; e < NE; e++) mm = fmaxf(mm, v[e]);
        float pr[NE], d2 = 0.f;
        for (int e = 0; e < NE; e++) { pr[e] = expf(v[e] - mm); d2 += pr[e]; }
        for (int e = 0; e < NE; e++) atomicAdd(&g_ctr.imp[e], pr[e] / d2);
        int jm = 0;
        for (int k = 1; k < NK; k++) if (idx[k] > idx[jm]) jm = k;
        atomicAdd(&g_ctr.loadcnt[jm], 1);
        for (int k = 0; k < NK; k++) {
            int e = idx[k];
            int slot = atomicAdd(&g_ctr.counts[e], 1);
            g_tok[e][slot]  = s;
            g_gate[e][slot] = w4[k];
        }
    }
}

// ---------------- GEMM1: 128m x 128f, B interleaved (up|gate per 8-col granule) ----------------
__global__ void __launch_bounds__(256, 1) g1_kernel(const float* __restrict__ bin) {
    extern __shared__ __align__(16) char dsm[];
    __shared__ int toks[128];
    __shared__ float bUs[128], bGs[128];
    const int e = blockIdx.z, m0 = blockIdx.x * 128, nf0 = blockIdx.y * 128;
    const int cnt = g_ctr.counts[e];
    if (m0 >= cnt) return;
    const int tid = threadIdx.x;
    if (tid < 128) {
        int r = m0 + tid;
        toks[tid] = (r < cnt) ? g_tok[e][r] : g_tok[e][0];
        bUs[tid] = bin[(size_t)e * 2 * FFD + nf0 + tid];
    } else {
        bGs[tid - 128] = bin[(size_t)e * 2 * FFD + FFD + nf0 + (tid - 128)];
    }
    __syncthreads();

    const uint32_t smu = s2u(dsm);
    const __half* Wb = g_win_h + (size_t)e * HD * (2 * FFD);

    auto load_chunk = [&](int c, int s) {
        const int k0 = c * 64;
        const uint32_t ab = smu + (uint32_t)s * STAGE, bb = ab + ATILE;
        #pragma unroll
        for (int g = 0; g < 4; g++) {
            int gg = g * 256 + tid, r = gg >> 3, cc = gg & 7;
            cpa16(ab + (uint32_t)(r * ARB + cc * 16),
                  g_xh + (size_t)toks[r] * HD + k0 + cc * 8);
        }
        #pragma unroll
        for (int g = 0; g < 8; g++) {
            int gg = g * 256 + tid, r = gg >> 5, g32 = gg & 31;
            int t = g32 >> 1;
            int n = ((g32 & 1) == 0) ? (nf0 + t * 8) : (FFD + nf0 + t * 8);
            cpa16(bb + (uint32_t)(r * BRB + g32 * 16),
                  Wb + (size_t)(k0 + r) * (2 * FFD) + n);
        }
        cpa_commit();
    };

    const int wid = tid >> 5, lane = tid & 31;
    const int wm = wid >> 2, wn = wid & 3;
    const int gq = lane >> 2, tg = lane & 3;
    const int rsel = lane & 7, seg = (lane >> 3) & 1, hsel = lane >> 4;
    const uint32_t aoff = (uint32_t)((rsel + seg * 8) * ARB + hsel * 16);
    const uint32_t boff = (uint32_t)((lane & 15) * BRB + (lane >> 4) * 16);
    float acc[4][8][4] = {};

    load_chunk(0, 0); load_chunk(1, 1);
    #pragma unroll 1
    for (int c = 0; c < NCH; c++) {
        if (c == NCH - 1) cpa_wait<0>(); else cpa_wait<1>();
        __syncthreads();
        if (c + 2 < NCH) load_chunk(c + 2, (c + 2) % 3);
        const uint32_t st = smu + (uint32_t)(c % 3) * STAGE;
        const uint32_t abase = st + (uint32_t)(wm * 64 * ARB) + aoff;
        const uint32_t bbase = st + ATILE + (uint32_t)(wn * 128) + boff;
        #pragma unroll
        for (int k16 = 0; k16 < 4; k16++) {
            uint32_t a[4][4];
            #pragma unroll
            for (int i = 0; i < 4; i++) ldsm4(a[i], abase + i * 16 * ARB + k16 * 32);
            #pragma unroll
            for (int j2 = 0; j2 < 4; j2++) {
                uint32_t b4[4];
                ldsm4t(b4, bbase + k16 * 16 * BRB + j2 * 32);
                #pragma unroll
                for (int i = 0; i < 4; i++) {
                    mma_f16(acc[i][2*j2],     a[i], &b4[0]);
                    mma_f16(acc[i][2*j2 + 1], a[i], &b4[2]);
                }
            }
        }
    }

    // register-resident SwiGLU epilogue, coalesced half2 stores
    const int mlim = cnt - m0;
    float2 bu[4], bg[4];
    #pragma unroll
    for (int p = 0; p < 4; p++) {
        int f0 = wn * 32 + p * 8 + 2 * tg;
        bu[p] = *(float2*)&bUs[f0];
        bg[p] = *(float2*)&bGs[f0];
    }
    #pragma unroll
    for (int i = 0; i < 4; i++) {
        int r0 = wm * 64 + i * 16 + gq;
        #pragma unroll
        for (int h = 0; h < 2; h++) {
            int row = r0 + h * 8;
            if (row < mlim) {
                __half* arow = g_act_h + ((size_t)e * TS + m0 + row) * FFD + nf0;
                #pragma unroll
                for (int p = 0; p < 4; p++) {
                    int f0 = wn * 32 + p * 8 + 2 * tg;
                    float up0 = acc[i][2*p][2*h]     + bu[p].x;
                    float up1 = acc[i][2*p][2*h + 1] + bu[p].y;
                    float gt0 = acc[i][2*p+1][2*h]     + bg[p].x;
                    float gt1 = acc[i][2*p+1][2*h + 1] + bg[p].y;
                    up0 = fminf(fmaxf(up0, -7.f), 7.f);
                    up1 = fminf(fmaxf(up1, -7.f), 7.f);
                    gt0 = fminf(fmaxf(gt0, -7.f), 7.f);
                    gt1 = fminf(fmaxf(gt1, -7.f), 7.f);
                    float o0 = gt0 / (1.f + expf(-gt0)) * up0;
                    float o1 = gt1 / (1.f + expf(-gt1)) * up1;
                    *(__half2*)(arow + f0) = __floats2half2_rn(o0, o1);
                }
            }
        }
    }
}

// ---------------- GEMM2: 128m x 256n, warp 64x64, weighted atomic scatter + aux ----------------
__global__ void __launch_bounds__(256, 1) g2_kernel(const float* __restrict__ bout,
                                                    float* __restrict__ out, int out_size) {
    extern __shared__ __align__(16) char dsm[];
    __shared__ int toks[128];
    __shared__ float gws[128];
    const int e = blockIdx.z, m0 = blockIdx.x * 128, n0 = blockIdx.y * 256;
    const int tid = threadIdx.x;
    if (e == 0 && blockIdx.x == 0 && blockIdx.y == 0 && tid == 0 && out_size > TS * HD) {
        float a = 0.f;
        #pragma unroll
        for (int j = 0; j < NK; j++)
            a += (g_ctr.imp[j] / (float)TS) * ((float)g_ctr.loadcnt[j] / (float)TS);
        out[TS * HD] = 0.02f * (float)NE * a;
    }
    const int cnt = g_ctr.counts[e];
    if (m0 >= cnt) return;
    if (tid < 128) {
        int r = m0 + tid;
        toks[tid] = (r < cnt) ? g_tok[e][r] : 0;
        gws[tid]  = (r < cnt) ? g_gate[e][r] : 0.f;
    }
    __syncthreads();

    const uint32_t smu = s2u(dsm);
    const __half* Wb = g_wout_h + (size_t)e * FFD * HD;
    const __half* Arows = g_act_h + ((size_t)e * TS + m0) * FFD;

    auto load_chunk = [&](int c, int s) {
        const int k0 = c * 64;
        const uint32_t ab = smu + (uint32_t)s * STAGE, bb = ab + ATILE;
        #pragma unroll
        for (int g = 0; g < 4; g++) {
            int gg = g * 256 + tid, r = gg >> 3, cc = gg & 7;
            cpa16(ab + (uint32_t)(r * ARB + cc * 16),
                  Arows + (size_t)r * FFD + k0 + cc * 8);
        }
        #pragma unroll
        for (int g = 0; g < 8; g++) {
            int gg = g * 256 + tid, r = gg >> 5, g32 = gg & 31;
            cpa16(bb + (uint32_t)(r * BRB + g32 * 16),
                  Wb + (size_t)(k0 + r) * HD + n0 + g32 * 8);
        }
        cpa_commit();
    };

    const int wid = tid >> 5, lane = tid & 31;
    const int wm = wid >> 2, wn = wid & 3;
    const int gq = lane >> 2, tg = lane & 3;
    const int rsel = lane & 7, seg = (lane >> 3) & 1, hsel = lane >> 4;
    const uint32_t aoff = (uint32_t)((rsel + seg * 8) * ARB + hsel * 16);
    const uint32_t boff = (uint32_t)((lane & 15) * BRB + (lane >> 4) * 16);
    float acc[4][8][4] = {};

    load_chunk(0, 0); load_chunk(1, 1);
    #pragma unroll 1
    for (int c = 0; c < NCH; c++) {
        if (c == NCH - 1) cpa_wait<0>(); else cpa_wait<1>();
        __syncthreads();
        if (c + 2 < NCH) load_chunk(c + 2, (c + 2) % 3);
        const uint32_t st = smu + (uint32_t)(c % 3) * STAGE;
        const uint32_t abase = st + (uint32_t)(wm * 64 * ARB) + aoff;
        const uint32_t bbase = st + ATILE + (uint32_t)(wn * 128) + boff;
        #pragma unroll
        for (int k16 = 0; k16 < 4; k16++) {
            uint32_t a[4][4];
            #pragma unroll
            for (int i = 0; i < 4; i++) ldsm4(a[i], abase + i * 16 * ARB + k16 * 32);
            #pragma unroll
            for (int j2 = 0; j2 < 4; j2++) {
                uint32_t b4[4];
                ldsm4t(b4, bbase + k16 * 16 * BRB + j2 * 32);
                #pragma unroll
                for (int i = 0; i < 4; i++) {
                    mma_f16(acc[i][2*j2],     a[i], &b4[0]);
                    mma_f16(acc[i][2*j2 + 1], a[i], &b4[2]);
                }
            }
        }
    }

    const float* bo = bout + (size_t)e * HD + n0;
    #pragma unroll
    for (int i = 0; i < 4; i++) {
        int r0 = wm * 64 + i * 16 + gq;
        #pragma unroll
        for (int h = 0; h < 2; h++) {
            int row = r0 + h * 8;
            if (m0 + row < cnt) {
                float gw = gws[row];
                float* orow = out + (size_t)toks[row] * HD + n0;
                #pragma unroll
                for (int j = 0; j < 8; j++) {
                    int c0 = wn * 64 + j * 8 + 2 * tg;
                    atomicAdd(&orow[c0],     gw * (acc[i][j][2 * h]     + bo[c0]));
                    atomicAdd(&orow[c0 + 1], gw * (acc[i][j][2 * h + 1] + bo[c0 + 1]));
                }
            }
        }
    }
}

// ---------------- launcher: 4 graph nodes ----------------
extern "C" void kernel_launch(void* const* d_in, const int* in_sizes, int n_in,
                              void* d_out, int out_size) {
    const float* x    = (const float*)d_in[0];
    const float* Win  = (const float*)d_in[1];
    const float* bin  = (const float*)d_in[2];
    const float* Wout = (const float*)d_in[3];
    const float* bout = (const float*)d_in[4];
    const float* rw   = (const float*)d_in[5];
    const float* rb   = (const float*)d_in[6];
    float* out = (float*)d_out;

    cudaFuncSetAttribute(g1_kernel, cudaFuncAttributeMaxDynamicSharedMemorySize, DSMEM);
    cudaFuncSetAttribute(g2_kernel, cudaFuncAttributeMaxDynamicSharedMemorySize, DSMEM);

    const int wblocks = (NE * HD * 2 * FFD + NE * FFD * HD) / 8 / 256;  // 24576
    const int zblocks = (out_size + 2047) / 2048;
    conv_kernel<<<wblocks + zblocks, 256>>>(Win, Wout, out, out_size, wblocks);  // 1 (+zero ctr, +zero out)
    router_kernel<<<TS / RTOK, 256>>>(x, rw, rb);                                 // 2
    g1_kernel<<<dim3(TS / 128, FFD / 128, NE), 256, DSMEM>>>(bin);                // 3
    g2_kernel<<<dim3(TS / 128, HD / 256, NE), 256, DSMEM>>>(bout, out, out_size); // 4 <- profiled
}